// round 2
// baseline (speedup 1.0000x reference)
#include <cuda_runtime.h>
#include <cuda_bf16.h>

#define NN 100000
#define NE 1600000
#define BN_EPS 1e-5f

// ---------------- scratch (static device memory, no allocs) ----------------
__device__ float4 g_agg[NN * 16];   // up to 64 floats/node (layer 1)
__device__ float4 g_h[NN * 8];      // 32 floats/node, pre-norm ReLU output
__device__ float  g_stats[5 * 64];  // per layer: sum[32], sumsq[32]
__device__ float  g_ab[64];         // a[32], b[32] for lazy BN of current h
__device__ float4 g_pool[64 * 8];   // graph pooled features

// vector reduction (no return) into global memory
__device__ __forceinline__ void red_add_f32x4(float4* addr, float4 v) {
    asm volatile("red.global.add.v4.f32 [%0], {%1, %2, %3, %4};"
                 :: "l"(addr), "f"(v.x), "f"(v.y), "f"(v.z), "f"(v.w)
                 : "memory");
}

// ---------------- zero accumulators (must run every replay) ----------------
__global__ void zero_kernel() {
    int i = blockIdx.x * blockDim.x + threadIdx.x;
    if (i < 5 * 64) g_stats[i] = 0.f;
    if (i < 64 * 8) g_pool[i] = make_float4(0.f, 0.f, 0.f, 0.f);
}

// ---------------- aggregation: agg[i] = n(h[i]); agg[dst] += n(h[src]) -----
// C = floats/4 per node row (16 for F=64, 8 for F=32). NORM applies lazy BN.
template<int C, bool NORM>
__global__ void agg_init_kernel(const float4* __restrict__ feat) {
    int i = blockIdx.x * blockDim.x + threadIdx.x;
    if (i >= NN * C) return;
    const float4* f = NORM ? (const float4*)g_h : feat;
    float4 v = f[i];
    if (NORM) {
        int c = (i & (C - 1)) * 4;
        v.x = v.x * g_ab[c + 0] + g_ab[32 + c + 0];
        v.y = v.y * g_ab[c + 1] + g_ab[32 + c + 1];
        v.z = v.z * g_ab[c + 2] + g_ab[32 + c + 2];
        v.w = v.w * g_ab[c + 3] + g_ab[32 + c + 3];
    }
    g_agg[i] = v;
}

template<int C, bool NORM>
__global__ void agg_edge_kernel(const float4* __restrict__ feat,
                                const int* __restrict__ srcs,
                                const int* __restrict__ dsts) {
    unsigned tid = blockIdx.x * blockDim.x + threadIdx.x;
    if (tid >= (unsigned)NE * C) return;
    unsigned e = tid / C;          // C is a power of 2 -> shift
    unsigned c = tid & (C - 1);
    int s = srcs[e];
    int d = dsts[e];
    const float4* f = NORM ? (const float4*)g_h : feat;
    float4 v = f[(size_t)s * C + c];
    if (NORM) {
        int col = c * 4;
        v.x = v.x * g_ab[col + 0] + g_ab[32 + col + 0];
        v.y = v.y * g_ab[col + 1] + g_ab[32 + col + 1];
        v.z = v.z * g_ab[col + 2] + g_ab[32 + col + 2];
        v.w = v.w * g_ab[col + 3] + g_ab[32 + col + 3];
    }
    red_add_f32x4(&g_agg[(size_t)d * C + c], v);
}

// ---------------- MLP: h = relu( relu(agg@Wa+Ba) @ Wb + Bb ) ---------------
template<int F>
__global__ void mlp_kernel(const float* __restrict__ Wa, const float* __restrict__ Ba,
                           const float* __restrict__ Wb, const float* __restrict__ Bb) {
    __shared__ float sWa[F * 32];
    __shared__ float sWb[32 * 32];
    __shared__ float sBa[32];
    __shared__ float sBb[32];
    for (int i = threadIdx.x; i < F * 32; i += blockDim.x) sWa[i] = Wa[i];
    for (int i = threadIdx.x; i < 1024;   i += blockDim.x) sWb[i] = Wb[i];
    if (threadIdx.x < 32) { sBa[threadIdx.x] = Ba[threadIdx.x]; sBb[threadIdx.x] = Bb[threadIdx.x]; }
    __syncthreads();

    int node = blockIdx.x * blockDim.x + threadIdx.x;
    if (node >= NN) return;

    const float4* row = g_agg + (size_t)node * (F / 4);
    float t[32];
    #pragma unroll
    for (int k = 0; k < 32; k++) t[k] = sBa[k];

    for (int j4 = 0; j4 < F / 4; j4++) {
        float4 xv = row[j4];
        const float* w = &sWa[j4 * 4 * 32];
        #pragma unroll
        for (int k = 0; k < 32; k++) t[k] += xv.x * w[k];
        #pragma unroll
        for (int k = 0; k < 32; k++) t[k] += xv.y * w[32 + k];
        #pragma unroll
        for (int k = 0; k < 32; k++) t[k] += xv.z * w[64 + k];
        #pragma unroll
        for (int k = 0; k < 32; k++) t[k] += xv.w * w[96 + k];
    }
    #pragma unroll
    for (int k = 0; k < 32; k++) t[k] = fmaxf(t[k], 0.f);

    float o[32];
    #pragma unroll
    for (int k = 0; k < 32; k++) o[k] = sBb[k];
    #pragma unroll
    for (int j = 0; j < 32; j++) {
        float tj = t[j];
        const float* w = &sWb[j * 32];
        #pragma unroll
        for (int k = 0; k < 32; k++) o[k] += tj * w[k];
    }

    float4* out = g_h + (size_t)node * 8;
    #pragma unroll
    for (int c = 0; c < 8; c++) {
        out[c] = make_float4(fmaxf(o[4*c+0], 0.f), fmaxf(o[4*c+1], 0.f),
                             fmaxf(o[4*c+2], 0.f), fmaxf(o[4*c+3], 0.f));
    }
}

// ---------------- per-column sum / sumsq over g_h ---------------------------
__global__ void stats_kernel(int l) {
    const float* h = reinterpret_cast<const float*>(g_h);
    int col = threadIdx.x & 31;
    int grp = threadIdx.x >> 5;   // 8 row-groups per block
    float s = 0.f, q = 0.f;
    for (int r = blockIdx.x * 8 + grp; r < NN; r += gridDim.x * 8) {
        float v = h[r * 32 + col];
        s += v; q += v * v;
    }
    __shared__ float sh[512];
    sh[threadIdx.x] = s;
    sh[256 + threadIdx.x] = q;
    __syncthreads();
    if (threadIdx.x < 32) {
        float S = 0.f, Q = 0.f;
        #pragma unroll
        for (int g = 0; g < 8; g++) {
            S += sh[g * 32 + threadIdx.x];
            Q += sh[256 + g * 32 + threadIdx.x];
        }
        atomicAdd(&g_stats[l * 64 + threadIdx.x], S);
        atomicAdd(&g_stats[l * 64 + 32 + threadIdx.x], Q);
    }
}

// ---------------- BN coefficients: h_norm = h*a + b -------------------------
__global__ void finalize_kernel(int l, const float* __restrict__ bn_g,
                                const float* __restrict__ bn_b) {
    int c = threadIdx.x;
    if (c >= 32) return;
    float sum = g_stats[l * 64 + c];
    float sq  = g_stats[l * 64 + 32 + c];
    const float invN = 1.f / (float)NN;
    float mu  = sum * invN;
    float var = sq * invN - mu * mu;
    float a = bn_g[l * 32 + c] * rsqrtf(var + BN_EPS);
    g_ab[c]      = a;
    g_ab[32 + c] = bn_b[l * 32 + c] - mu * a;
}

// ---------------- global add pool over graphs (with lazy BN) ----------------
__global__ void pool_kernel(const int* __restrict__ batch) {
    int tid = blockIdx.x * blockDim.x + threadIdx.x;
    if (tid >= NN * 8) return;
    int n = tid >> 3, c = tid & 7;
    float4 v = g_h[(size_t)n * 8 + c];
    int col = c * 4;
    v.x = v.x * g_ab[col + 0] + g_ab[32 + col + 0];
    v.y = v.y * g_ab[col + 1] + g_ab[32 + col + 1];
    v.z = v.z * g_ab[col + 2] + g_ab[32 + col + 2];
    v.w = v.w * g_ab[col + 3] + g_ab[32 + col + 3];
    int g = batch[n];
    red_add_f32x4(&g_pool[g * 8 + c], v);
}

// ---------------- head: out = relu(g@fc1+b1) @ fc2 + b2 ---------------------
__global__ void head_kernel(const float* __restrict__ fc1w, const float* __restrict__ fc1b,
                            const float* __restrict__ fc2w, const float* __restrict__ fc2b,
                            float* __restrict__ out) {
    int g = threadIdx.x;
    if (g >= 64) return;
    float in[32];
    #pragma unroll
    for (int j = 0; j < 8; j++) {
        float4 v = g_pool[g * 8 + j];
        in[4*j+0] = v.x; in[4*j+1] = v.y; in[4*j+2] = v.z; in[4*j+3] = v.w;
    }
    float t[32];
    #pragma unroll
    for (int k = 0; k < 32; k++) t[k] = fc1b[k];
    #pragma unroll
    for (int j = 0; j < 32; j++) {
        float xv = in[j];
        #pragma unroll
        for (int k = 0; k < 32; k++) t[k] += xv * fc1w[j * 32 + k];
    }
    #pragma unroll
    for (int k = 0; k < 32; k++) t[k] = fmaxf(t[k], 0.f);
    float o[10];
    #pragma unroll
    for (int c = 0; c < 10; c++) o[c] = fc2b[c];
    #pragma unroll
    for (int j = 0; j < 32; j++) {
        float xv = t[j];
        #pragma unroll
        for (int c = 0; c < 10; c++) o[c] += xv * fc2w[j * 10 + c];
    }
    #pragma unroll
    for (int c = 0; c < 10; c++) out[g * 10 + c] = o[c];
}

// ---------------- launch ----------------------------------------------------
extern "C" void kernel_launch(void* const* d_in, const int* in_sizes, int n_in,
                              void* d_out, int out_size) {
    const float* x     = (const float*)d_in[0];
    const int*   ei    = (const int*)d_in[1];     // int32! (JAX x64 disabled)
    const int*   batch = (const int*)d_in[2];     // int32!
    const float* w1a = (const float*)d_in[3];
    const float* b1a = (const float*)d_in[4];
    const float* w1b = (const float*)d_in[5];
    const float* b1b = (const float*)d_in[6];
    const float* Wa  = (const float*)d_in[7];
    const float* Ba  = (const float*)d_in[8];
    const float* Wb  = (const float*)d_in[9];
    const float* Bb  = (const float*)d_in[10];
    const float* bng = (const float*)d_in[11];
    const float* bnb = (const float*)d_in[12];
    const float* fc1w = (const float*)d_in[13];
    const float* fc1b = (const float*)d_in[14];
    const float* fc2w = (const float*)d_in[15];
    const float* fc2b = (const float*)d_in[16];
    float* out = (float*)d_out;

    const int* srcs = ei;
    const int* dsts = ei + NE;

    zero_kernel<<<2, 256>>>();

    // ---- layer 1: F=64 input (raw x, no BN on input) ----
    {
        int n_init = NN * 16;
        agg_init_kernel<16, false><<<(n_init + 255) / 256, 256>>>((const float4*)x);
        unsigned n_edge = (unsigned)NE * 16;
        agg_edge_kernel<16, false><<<(n_edge + 255) / 256, 256>>>((const float4*)x, srcs, dsts);
        mlp_kernel<64><<<(NN + 255) / 256, 256>>>(w1a, b1a, w1b, b1b);
        stats_kernel<<<256, 256>>>(0);
        finalize_kernel<<<1, 32>>>(0, bng, bnb);
    }

    // ---- layers 2-5: F=32, lazy-BN'd h feeds aggregation ----
    for (int l = 1; l <= 4; l++) {
        int li = l - 1;
        int n_init = NN * 8;
        agg_init_kernel<8, true><<<(n_init + 255) / 256, 256>>>(nullptr);
        unsigned n_edge = (unsigned)NE * 8;
        agg_edge_kernel<8, true><<<(n_edge + 255) / 256, 256>>>(nullptr, srcs, dsts);
        mlp_kernel<32><<<(NN + 255) / 256, 256>>>(Wa + li * 1024, Ba + li * 32,
                                                  Wb + li * 1024, Bb + li * 32);
        stats_kernel<<<256, 256>>>(l);
        finalize_kernel<<<1, 32>>>(l, bng, bnb);
    }

    // ---- pool + head ----
    pool_kernel<<<(NN * 8 + 255) / 256, 256>>>(batch);
    head_kernel<<<1, 64>>>(fc1w, fc1b, fc2w, fc2b, out);
}

// round 3
// speedup vs baseline: 1.2058x; 1.2058x over previous
#include <cuda_runtime.h>
#include <cuda_bf16.h>

#define NN 100000
#define NE 1600000
#define BN_EPS 1e-5f
#define SCAN_BLK 1024          // elements per scan block
#define N_SCAN_BLKS ((NN + SCAN_BLK - 1) / SCAN_BLK)   // 98

// ---------------- scratch (static device memory, no allocs) ----------------
__device__ float4 g_agg[NN * 16];    // up to 64 floats/node (layer 1)
__device__ float4 g_h[NN * 8];       // 32 floats/node, pre-norm ReLU output
__device__ float  g_stats[5 * 64];   // per layer: sum[32], sumsq[32]
__device__ float  g_ab[64];          // a[32], b[32] lazy-BN coefficients
__device__ float4 g_pool[64 * 8];    // graph pooled features
// CSR build
__device__ int g_cnt[NN];            // degree histogram
__device__ int g_excl[NN];           // per-block exclusive prefix
__device__ int g_bsum[128];          // per-block totals
__device__ int g_boff[128];          // exclusive block offsets
__device__ int g_rs[NN + 1];         // row_start
__device__ int g_cur[NN];            // fill cursors
__device__ int g_col[NE];            // CSR column (src) indices

__device__ __forceinline__ void red_add_f32x4(float4* addr, float4 v) {
    asm volatile("red.global.add.v4.f32 [%0], {%1, %2, %3, %4};"
                 :: "l"(addr), "f"(v.x), "f"(v.y), "f"(v.z), "f"(v.w)
                 : "memory");
}

// ---------------- zero accumulators + histogram ----------------------------
__global__ void zero_kernel() {
    int i = blockIdx.x * blockDim.x + threadIdx.x;
    if (i < NN) g_cnt[i] = 0;
    if (i < 5 * 64) g_stats[i] = 0.f;
    if (i < 64 * 8) g_pool[i] = make_float4(0.f, 0.f, 0.f, 0.f);
}

// ---------------- CSR build -------------------------------------------------
__global__ void count_kernel(const int* __restrict__ dsts) {
    int e = blockIdx.x * blockDim.x + threadIdx.x;
    if (e < NE) atomicAdd(&g_cnt[dsts[e]], 1);
}

// per-1024-element block scan: 256 threads x 4 elements
__global__ void scan_a_kernel() {
    __shared__ int wsum[8];
    int base = blockIdx.x * SCAN_BLK + threadIdx.x * 4;
    int v0 = (base + 0 < NN) ? g_cnt[base + 0] : 0;
    int v1 = (base + 1 < NN) ? g_cnt[base + 1] : 0;
    int v2 = (base + 2 < NN) ? g_cnt[base + 2] : 0;
    int v3 = (base + 3 < NN) ? g_cnt[base + 3] : 0;
    int tsum = v0 + v1 + v2 + v3;
    int lane = threadIdx.x & 31, wid = threadIdx.x >> 5;
    int incl = tsum;
    #pragma unroll
    for (int off = 1; off < 32; off <<= 1) {
        int n = __shfl_up_sync(0xffffffffu, incl, off);
        if (lane >= off) incl += n;
    }
    if (lane == 31) wsum[wid] = incl;
    __syncthreads();
    if (wid == 0 && lane < 8) {
        int w = wsum[lane];
        #pragma unroll
        for (int off = 1; off < 8; off <<= 1) {
            int n = __shfl_up_sync(0xffu, w, off);
            if (lane >= off) w += n;
        }
        wsum[lane] = w;
    }
    __syncthreads();
    int off = (wid > 0 ? wsum[wid - 1] : 0) + incl - tsum;  // thread-exclusive
    if (base + 0 < NN) g_excl[base + 0] = off;
    if (base + 1 < NN) g_excl[base + 1] = off + v0;
    if (base + 2 < NN) g_excl[base + 2] = off + v0 + v1;
    if (base + 3 < NN) g_excl[base + 3] = off + v0 + v1 + v2;
    if (threadIdx.x == 0) g_bsum[blockIdx.x] = wsum[7];
}

__global__ void scan_b_kernel() {
    __shared__ int s[128];
    int t = threadIdx.x;
    int orig = (t < N_SCAN_BLKS) ? g_bsum[t] : 0;
    s[t] = orig;
    __syncthreads();
    #pragma unroll
    for (int off = 1; off < 128; off <<= 1) {
        int v = (t >= off) ? s[t - off] : 0;
        __syncthreads();
        s[t] += v;
        __syncthreads();
    }
    if (t < N_SCAN_BLKS) g_boff[t] = s[t] - orig;  // exclusive
}

__global__ void scan_c_kernel() {
    int i = blockIdx.x * blockDim.x + threadIdx.x;
    if (i < NN) {
        int rs = g_excl[i] + g_boff[i / SCAN_BLK];
        g_rs[i] = rs;
        g_cur[i] = rs;
    }
    if (i == 0) g_rs[NN] = NE;
}

__global__ void fill_kernel(const int* __restrict__ srcs,
                            const int* __restrict__ dsts) {
    int e = blockIdx.x * blockDim.x + threadIdx.x;
    if (e >= NE) return;
    int d = dsts[e];
    int pos = atomicAdd(&g_cur[d], 1);
    g_col[pos] = srcs[e];
}

// ---------------- gather aggregation (CSR) ---------------------------------
// C float4 channels per node (16 for F=64, 8 for F=32).
// agg[n] = n(feat[n]) + sum_{e in row(n)} n(feat[col[e]])
template<int C, bool NORM>
__global__ void gather_kernel(const float4* __restrict__ feat) {
    int tid = blockIdx.x * blockDim.x + threadIdx.x;
    int node = tid / C;
    int c = tid & (C - 1);
    if (node >= NN) return;
    const float4* f = NORM ? (const float4*)g_h : feat;

    float ax = 1.f, ay = 1.f, az = 1.f, aw = 1.f;
    float bx = 0.f, by = 0.f, bz = 0.f, bw = 0.f;
    if (NORM) {
        int c4 = c * 4;
        ax = g_ab[c4 + 0]; ay = g_ab[c4 + 1]; az = g_ab[c4 + 2]; aw = g_ab[c4 + 3];
        bx = g_ab[32 + c4 + 0]; by = g_ab[32 + c4 + 1];
        bz = g_ab[32 + c4 + 2]; bw = g_ab[32 + c4 + 3];
    }

    float4 self = f[(size_t)node * C + c];
    float sx, sy, sz, sw;
    if (NORM) {
        sx = fmaf(self.x, ax, bx); sy = fmaf(self.y, ay, by);
        sz = fmaf(self.z, az, bz); sw = fmaf(self.w, aw, bw);
    } else { sx = self.x; sy = self.y; sz = self.z; sw = self.w; }

    int e0 = g_rs[node], e1 = g_rs[node + 1];
    for (int e = e0; e < e1; e++) {
        int s = g_col[e];
        float4 v = f[(size_t)s * C + c];
        if (NORM) {
            sx = fmaf(v.x, ax, sx); sy = fmaf(v.y, ay, sy);
            sz = fmaf(v.z, az, sz); sw = fmaf(v.w, aw, sw);
            sx += bx; sy += by; sz += bz; sw += bw;
        } else {
            sx += v.x; sy += v.y; sz += v.z; sw += v.w;
        }
    }
    g_agg[(size_t)node * C + c] = make_float4(sx, sy, sz, sw);
}

// ---------------- MLP: h = relu( relu(agg@Wa+Ba) @ Wb + Bb ) ---------------
// 128 threads / 128 nodes per block; smem-staged input tile.
template<int F>
__global__ void mlp_kernel(const float* __restrict__ Wa, const float* __restrict__ Ba,
                           const float* __restrict__ Wb, const float* __restrict__ Bb) {
    __shared__ float sWa[F * 32];
    __shared__ float sWb[32 * 32];
    __shared__ float sBa[32];
    __shared__ float sBb[32];
    __shared__ float sx[128 * (F + 1)];

    for (int i = threadIdx.x; i < F * 32; i += 128) sWa[i] = Wa[i];
    for (int i = threadIdx.x; i < 1024;   i += 128) sWb[i] = Wb[i];
    if (threadIdx.x < 32) { sBa[threadIdx.x] = Ba[threadIdx.x]; sBb[threadIdx.x] = Bb[threadIdx.x]; }

    int node0 = blockIdx.x * 128;
    const float4* ga = g_agg;
    // coalesced tile load: 128 rows x F floats
    for (int idx = threadIdx.x; idx < 128 * (F / 4); idx += 128) {
        int row = idx / (F / 4);
        int cc = idx % (F / 4);
        if (node0 + row < NN) {
            float4 v = ga[(size_t)(node0 + row) * (F / 4) + cc];
            float* d = &sx[row * (F + 1) + cc * 4];
            d[0] = v.x; d[1] = v.y; d[2] = v.z; d[3] = v.w;
        }
    }
    __syncthreads();

    int node = node0 + threadIdx.x;
    if (node >= NN) return;

    const float* xr = &sx[threadIdx.x * (F + 1)];
    float t[32];
    #pragma unroll
    for (int k = 0; k < 32; k++) t[k] = sBa[k];
    for (int j = 0; j < F; j++) {
        float xv = xr[j];
        const float* w = &sWa[j * 32];
        #pragma unroll
        for (int k = 0; k < 32; k++) t[k] = fmaf(xv, w[k], t[k]);
    }
    #pragma unroll
    for (int k = 0; k < 32; k++) t[k] = fmaxf(t[k], 0.f);

    float4* out = g_h + (size_t)node * 8;
    #pragma unroll
    for (int h = 0; h < 2; h++) {
        float o[16];
        #pragma unroll
        for (int k = 0; k < 16; k++) o[k] = sBb[h * 16 + k];
        #pragma unroll
        for (int j = 0; j < 32; j++) {
            float tj = t[j];
            const float* w = &sWb[j * 32 + h * 16];
            #pragma unroll
            for (int k = 0; k < 16; k++) o[k] = fmaf(tj, w[k], o[k]);
        }
        #pragma unroll
        for (int q = 0; q < 4; q++) {
            out[h * 4 + q] = make_float4(fmaxf(o[4*q+0], 0.f), fmaxf(o[4*q+1], 0.f),
                                         fmaxf(o[4*q+2], 0.f), fmaxf(o[4*q+3], 0.f));
        }
    }
}

// ---------------- per-column sum / sumsq over g_h ---------------------------
__global__ void stats_kernel(int l) {
    const float* h = reinterpret_cast<const float*>(g_h);
    int col = threadIdx.x & 31;
    int grp = threadIdx.x >> 5;
    float s = 0.f, q = 0.f;
    for (int r = blockIdx.x * 8 + grp; r < NN; r += gridDim.x * 8) {
        float v = h[r * 32 + col];
        s += v; q += v * v;
    }
    __shared__ float sh[512];
    sh[threadIdx.x] = s;
    sh[256 + threadIdx.x] = q;
    __syncthreads();
    if (threadIdx.x < 32) {
        float S = 0.f, Q = 0.f;
        #pragma unroll
        for (int g = 0; g < 8; g++) {
            S += sh[g * 32 + threadIdx.x];
            Q += sh[256 + g * 32 + threadIdx.x];
        }
        atomicAdd(&g_stats[l * 64 + threadIdx.x], S);
        atomicAdd(&g_stats[l * 64 + 32 + threadIdx.x], Q);
    }
}

// ---------------- BN coefficients: h_norm = h*a + b -------------------------
__global__ void finalize_kernel(int l, const float* __restrict__ bn_g,
                                const float* __restrict__ bn_b) {
    int c = threadIdx.x;
    if (c >= 32) return;
    float sum = g_stats[l * 64 + c];
    float sq  = g_stats[l * 64 + 32 + c];
    const float invN = 1.f / (float)NN;
    float mu  = sum * invN;
    float var = sq * invN - mu * mu;
    float a = bn_g[l * 32 + c] * rsqrtf(var + BN_EPS);
    g_ab[c]      = a;
    g_ab[32 + c] = bn_b[l * 32 + c] - mu * a;
}

// ---------------- global add pool over graphs (with lazy BN) ----------------
__global__ void pool_kernel(const int* __restrict__ batch) {
    int tid = blockIdx.x * blockDim.x + threadIdx.x;
    if (tid >= NN * 8) return;
    int n = tid >> 3, c = tid & 7;
    float4 v = g_h[(size_t)n * 8 + c];
    int col = c * 4;
    v.x = fmaf(v.x, g_ab[col + 0], g_ab[32 + col + 0]);
    v.y = fmaf(v.y, g_ab[col + 1], g_ab[32 + col + 1]);
    v.z = fmaf(v.z, g_ab[col + 2], g_ab[32 + col + 2]);
    v.w = fmaf(v.w, g_ab[col + 3], g_ab[32 + col + 3]);
    int g = batch[n];
    red_add_f32x4(&g_pool[g * 8 + c], v);
}

// ---------------- head: out = relu(g@fc1+b1) @ fc2 + b2 ---------------------
__global__ void head_kernel(const float* __restrict__ fc1w, const float* __restrict__ fc1b,
                            const float* __restrict__ fc2w, const float* __restrict__ fc2b,
                            float* __restrict__ out) {
    int g = threadIdx.x;
    if (g >= 64) return;
    float in[32];
    #pragma unroll
    for (int j = 0; j < 8; j++) {
        float4 v = g_pool[g * 8 + j];
        in[4*j+0] = v.x; in[4*j+1] = v.y; in[4*j+2] = v.z; in[4*j+3] = v.w;
    }
    float t[32];
    #pragma unroll
    for (int k = 0; k < 32; k++) t[k] = fc1b[k];
    #pragma unroll
    for (int j = 0; j < 32; j++) {
        float xv = in[j];
        #pragma unroll
        for (int k = 0; k < 32; k++) t[k] = fmaf(xv, fc1w[j * 32 + k], t[k]);
    }
    #pragma unroll
    for (int k = 0; k < 32; k++) t[k] = fmaxf(t[k], 0.f);
    float o[10];
    #pragma unroll
    for (int c = 0; c < 10; c++) o[c] = fc2b[c];
    #pragma unroll
    for (int j = 0; j < 32; j++) {
        float xv = t[j];
        #pragma unroll
        for (int c = 0; c < 10; c++) o[c] = fmaf(xv, fc2w[j * 10 + c], o[c]);
    }
    #pragma unroll
    for (int c = 0; c < 10; c++) out[g * 10 + c] = o[c];
}

// ---------------- launch ----------------------------------------------------
extern "C" void kernel_launch(void* const* d_in, const int* in_sizes, int n_in,
                              void* d_out, int out_size) {
    const float* x     = (const float*)d_in[0];
    const int*   ei    = (const int*)d_in[1];     // int32 (JAX x64 disabled)
    const int*   batch = (const int*)d_in[2];
    const float* w1a = (const float*)d_in[3];
    const float* b1a = (const float*)d_in[4];
    const float* w1b = (const float*)d_in[5];
    const float* b1b = (const float*)d_in[6];
    const float* Wa  = (const float*)d_in[7];
    const float* Ba  = (const float*)d_in[8];
    const float* Wb  = (const float*)d_in[9];
    const float* Bb  = (const float*)d_in[10];
    const float* bng = (const float*)d_in[11];
    const float* bnb = (const float*)d_in[12];
    const float* fc1w = (const float*)d_in[13];
    const float* fc1b = (const float*)d_in[14];
    const float* fc2w = (const float*)d_in[15];
    const float* fc2b = (const float*)d_in[16];
    float* out = (float*)d_out;

    const int* srcs = ei;
    const int* dsts = ei + NE;

    // ---- CSR build (per replay) ----
    zero_kernel<<<(NN + 255) / 256, 256>>>();
    count_kernel<<<(NE + 255) / 256, 256>>>(dsts);
    scan_a_kernel<<<N_SCAN_BLKS, 256>>>();
    scan_b_kernel<<<1, 128>>>();
    scan_c_kernel<<<(NN + 255) / 256, 256>>>();
    fill_kernel<<<(NE + 255) / 256, 256>>>(srcs, dsts);

    // ---- layer 1: F=64 raw input ----
    gather_kernel<16, false><<<(NN * 16 + 255) / 256, 256>>>((const float4*)x);
    mlp_kernel<64><<<(NN + 127) / 128, 128>>>(w1a, b1a, w1b, b1b);
    stats_kernel<<<256, 256>>>(0);
    finalize_kernel<<<1, 32>>>(0, bng, bnb);

    // ---- layers 2-5: F=32, lazy-BN'd h ----
    for (int l = 1; l <= 4; l++) {
        int li = l - 1;
        gather_kernel<8, true><<<(NN * 8 + 255) / 256, 256>>>(nullptr);
        mlp_kernel<32><<<(NN + 127) / 128, 128>>>(Wa + li * 1024, Ba + li * 32,
                                                  Wb + li * 1024, Bb + li * 32);
        stats_kernel<<<256, 256>>>(l);
        finalize_kernel<<<1, 32>>>(l, bng, bnb);
    }

    // ---- pool + head ----
    pool_kernel<<<(NN * 8 + 255) / 256, 256>>>(batch);
    head_kernel<<<1, 64>>>(fc1w, fc1b, fc2w, fc2b, out);
}